// round 3
// baseline (speedup 1.0000x reference)
#include <cuda_runtime.h>

#define E_DIM 1024
#define D_DIM 64
#define B_DIM 4
#define T_DIM 4096
#define M_ROWS (B_DIM * T_DIM)   // 16384

typedef unsigned long long ull;

// Scratch for Q, K, V: [B*T, D] fp32 each. Device globals (no allocs).
__device__ float g_q[M_ROWS * D_DIM];
__device__ float g_k[M_ROWS * D_DIM];
__device__ float g_v[M_ROWS * D_DIM];

// ---------------- packed f32x2 helpers ----------------
__device__ __forceinline__ void ffma2(ull& d, ull a, ull b) {
    asm("fma.rn.f32x2 %0, %1, %2, %0;" : "+l"(d) : "l"(a), "l"(b));
}
__device__ __forceinline__ ull mul2(ull a, ull b) {
    ull r; asm("mul.rn.f32x2 %0, %1, %2;" : "=l"(r) : "l"(a), "l"(b)); return r;
}
__device__ __forceinline__ ull dup2(float x) {
    ull r; asm("mov.b64 %0, {%1, %1};" : "=l"(r) : "f"(x)); return r;
}
__device__ __forceinline__ ull pack2(float lo, float hi) {
    ull r; asm("mov.b64 %0, {%1, %2};" : "=l"(r) : "f"(lo), "f"(hi)); return r;
}
__device__ __forceinline__ void unpack2(ull v, float& lo, float& hi) {
    asm("mov.b64 {%0, %1}, %2;" : "=f"(lo), "=f"(hi) : "l"(v));
}
__device__ __forceinline__ void cp_async16(unsigned smem_addr, const void* gptr) {
    asm volatile("cp.async.ca.shared.global [%0], [%1], 16;" :: "r"(smem_addr), "l"(gptr));
}
__device__ __forceinline__ void cp_commit() {
    asm volatile("cp.async.commit_group;");
}
__device__ __forceinline__ void cp_wait0() {
    asm volatile("cp.async.wait_group 0;");
}

// ---------------------------------------------------------------------------
// Kernel 1: QKV projection.  C[m, d] = sum_e x[m, e] * W[e, d]
// Block tile 128x64, BK=32, 256 threads. Per-thread 8(m) x 4(n), packed pairs
// along m via fma.rn.f32x2. A tile stored transposed [k][m] with XOR swizzle.
// ---------------------------------------------------------------------------
__global__ __launch_bounds__(256)
void qkv_kernel(const float* __restrict__ x,
                const float* __restrict__ Wq,
                const float* __restrict__ Wk,
                const float* __restrict__ Wv)
{
    constexpr int BM = 128, BK = 32, BN = 64;
    __shared__ float As[BK * BM];   // transposed [k][m], swizzled
    __shared__ float Bs[BK * BN];   // natural [k][n]

    const int tid = threadIdx.x;
    const int ty  = tid >> 4;        // 0..15 -> rows ty*8 .. +7
    const int tx  = tid & 15;        // 0..15 -> cols tx*4 .. +3
    const int ty2 = ty << 1;
    const int m0  = blockIdx.x * BM;

    const float* W;
    float* C;
    if (blockIdx.y == 0)      { W = Wq; C = g_q; }
    else if (blockIdx.y == 1) { W = Wk; C = g_k; }
    else                      { W = Wv; C = g_v; }

    ull acc[4][4];
    #pragma unroll
    for (int p = 0; p < 4; p++)
        #pragma unroll
        for (int j = 0; j < 4; j++) acc[p][j] = 0ULL;

    // prefetch first tiles into regs
    float4 xr[4], wr[2];
    #pragma unroll
    for (int i = 0; i < 4; i++) {
        int f = tid + 256 * i;                 // 0..1023
        int m = f >> 3;                        // 0..127
        int kc = (f & 7) << 2;                 // 0..28
        xr[i] = *reinterpret_cast<const float4*>(&x[(size_t)(m0 + m) * E_DIM + kc]);
    }
    #pragma unroll
    for (int i = 0; i < 2; i++) {
        int f = tid + 256 * i;                 // 0..511
        int r = f >> 4;                        // 0..31
        int c4 = (f & 15) << 2;                // 0..60
        wr[i] = *reinterpret_cast<const float4*>(&W[(size_t)r * BN + c4]);
    }

    for (int k0 = 0; k0 < E_DIM; k0 += BK) {
        __syncthreads();
        // store A transposed + swizzled: phys = k*128 + ((m>>2)^((k>>2)&7))*4 + (m&3)
        #pragma unroll
        for (int i = 0; i < 4; i++) {
            int f = tid + 256 * i;
            int m = f >> 3;
            int kc = (f & 7) << 2;
            int slot = ((m >> 2) ^ (f & 7)) << 2;   // (kc+c)>>2 = f&7 for c<4
            int ml = m & 3;
            As[(kc + 0) * BM + slot + ml] = xr[i].x;
            As[(kc + 1) * BM + slot + ml] = xr[i].y;
            As[(kc + 2) * BM + slot + ml] = xr[i].z;
            As[(kc + 3) * BM + slot + ml] = xr[i].w;
        }
        #pragma unroll
        for (int i = 0; i < 2; i++) {
            int f = tid + 256 * i;
            int r = f >> 4;
            int c4 = (f & 15) << 2;
            *reinterpret_cast<float4*>(&Bs[r * BN + c4]) = wr[i];
        }
        // prefetch next tile
        if (k0 + BK < E_DIM) {
            #pragma unroll
            for (int i = 0; i < 4; i++) {
                int f = tid + 256 * i;
                int m = f >> 3;
                int kc = (f & 7) << 2;
                xr[i] = *reinterpret_cast<const float4*>(
                    &x[(size_t)(m0 + m) * E_DIM + k0 + BK + kc]);
            }
            #pragma unroll
            for (int i = 0; i < 2; i++) {
                int f = tid + 256 * i;
                int r = f >> 4;
                int c4 = (f & 15) << 2;
                wr[i] = *reinterpret_cast<const float4*>(
                    &W[(size_t)(k0 + BK + r) * BN + c4]);
            }
        }
        __syncthreads();

        #pragma unroll 2
        for (int k4 = 0; k4 < BK / 4; k4++) {
            const int g = k4 & 7;
            const int sa0 = ((ty2 + 0) ^ g) << 2;
            const int sa1 = ((ty2 + 1) ^ g) << 2;
            #pragma unroll
            for (int kk = 0; kk < 4; kk++) {
                const int k = (k4 << 2) + kk;
                const float* arow = As + k * BM;
                ulonglong2 a01 = *reinterpret_cast<const ulonglong2*>(arow + sa0);
                ulonglong2 a23 = *reinterpret_cast<const ulonglong2*>(arow + sa1);
                float4 bv = *reinterpret_cast<const float4*>(&Bs[k * BN + (tx << 2)]);
                ull b0 = dup2(bv.x), b1 = dup2(bv.y), b2 = dup2(bv.z), b3 = dup2(bv.w);
                ull ap[4] = {a01.x, a01.y, a23.x, a23.y};
                #pragma unroll
                for (int p = 0; p < 4; p++) {
                    ffma2(acc[p][0], ap[p], b0);
                    ffma2(acc[p][1], ap[p], b1);
                    ffma2(acc[p][2], ap[p], b2);
                    ffma2(acc[p][3], ap[p], b3);
                }
            }
        }
    }

    // epilogue
    #pragma unroll
    for (int p = 0; p < 4; p++) {
        float lo[4], hi[4];
        #pragma unroll
        for (int j = 0; j < 4; j++) unpack2(acc[p][j], lo[j], hi[j]);
        size_t r0 = (size_t)(m0 + ty * 8 + 2 * p) * D_DIM + (tx << 2);
        *reinterpret_cast<float4*>(&C[r0])         = make_float4(lo[0], lo[1], lo[2], lo[3]);
        *reinterpret_cast<float4*>(&C[r0 + D_DIM]) = make_float4(hi[0], hi[1], hi[2], hi[3]);
    }
}

// ---------------------------------------------------------------------------
// Kernel 2: fused flash attention. BM=BN=D=64, 128 threads.
// ty = tid>>4 (0..7): rows ty*8..+7 (4 packed pairs). tx = tid&15: cols tx*4..+3.
// Qs/Ks transposed [d][m] swizzled: phys = d*64 + ((m>>2)^((d>>2)&15))*4 + (m&3)
// Ps transposed [n][m] same swizzle. Vs natural, double-buffered via cp.async.
// K prefetched to regs one tile ahead.
// ---------------------------------------------------------------------------
__global__ __launch_bounds__(128)
void attn_kernel(float* __restrict__ out)
{
    constexpr int DD = 64, BN = 64;
    constexpr int NT = T_DIM / BN;   // 64 tiles

    extern __shared__ float sm[];
    float* Qs  = sm;                 // 4096
    float* Ks  = sm + 4096;          // 4096
    float* Ps  = sm + 8192;          // 4096
    float* Vs0 = sm + 12288;         // 4096
    float* Vs1 = sm + 16384;         // 4096

    const int tid = threadIdx.x;
    const int ty  = tid >> 4;        // 0..7
    const int tx  = tid & 15;        // 0..15
    const int ty2 = ty << 1;
    const int b   = blockIdx.y;
    const int q0  = blockIdx.x * 64;

    const float* Q = g_q + (size_t)b * T_DIM * DD;
    const float* K = g_k + (size_t)b * T_DIM * DD;
    const float* V = g_v + (size_t)b * T_DIM * DD;

    // loader geometry (per thread, 8 float4)
    int lrow[8], ld0[8], lslot[8];
    #pragma unroll
    for (int i = 0; i < 8; i++) {
        int f   = tid + 128 * i;
        lrow[i] = f >> 4;                          // 0..63
        ld0[i]  = (f & 15) << 2;                   // 0..60
        lslot[i] = (((f >> 4) >> 2) ^ (f & 15)) << 2;  // ((row>>2) ^ (d0>>2))*4
    }

    // ---- prologue: Q load+transpose, K prefetch, V cp.async tile 0 ----
    #pragma unroll
    for (int i = 0; i < 8; i++) {
        float4 v = *reinterpret_cast<const float4*>(&Q[(size_t)(q0 + lrow[i]) * DD + ld0[i]]);
        int ml = lrow[i] & 3;
        Qs[(ld0[i] + 0) * DD + lslot[i] + ml] = v.x;
        Qs[(ld0[i] + 1) * DD + lslot[i] + ml] = v.y;
        Qs[(ld0[i] + 2) * DD + lslot[i] + ml] = v.z;
        Qs[(ld0[i] + 3) * DD + lslot[i] + ml] = v.w;
    }
    float4 kr[8];
    #pragma unroll
    for (int i = 0; i < 8; i++)
        kr[i] = *reinterpret_cast<const float4*>(&K[(size_t)lrow[i] * DD + ld0[i]]);
    {
        unsigned vbase = (unsigned)__cvta_generic_to_shared(Vs0);
        #pragma unroll
        for (int i = 0; i < 8; i++)
            cp_async16(vbase + (unsigned)((lrow[i] * DD + ld0[i]) << 2),
                       &V[(size_t)lrow[i] * DD + ld0[i]]);
        cp_commit();
    }

    ull acc[4][4];
    float rmax[8], rsum[8];
    #pragma unroll
    for (int p = 0; p < 4; p++)
        #pragma unroll
        for (int j = 0; j < 4; j++) acc[p][j] = 0ULL;
    #pragma unroll
    for (int i = 0; i < 8; i++) { rmax[i] = -1e30f; rsum[i] = 0.f; }

    for (int t = 0; t < NT; t++) {
        float* Vcur = (t & 1) ? Vs1 : Vs0;
        float* Vnxt = (t & 1) ? Vs0 : Vs1;

        cp_wait0();
        __syncthreads();   // prev compute done; V(t) visible

        // store K(t) transposed + swizzled from regs
        #pragma unroll
        for (int i = 0; i < 8; i++) {
            int ml = lrow[i] & 3;
            Ks[(ld0[i] + 0) * DD + lslot[i] + ml] = kr[i].x;
            Ks[(ld0[i] + 1) * DD + lslot[i] + ml] = kr[i].y;
            Ks[(ld0[i] + 2) * DD + lslot[i] + ml] = kr[i].z;
            Ks[(ld0[i] + 3) * DD + lslot[i] + ml] = kr[i].w;
        }
        // prefetch next K / V
        if (t + 1 < NT) {
            const int n1 = (t + 1) * BN;
            #pragma unroll
            for (int i = 0; i < 8; i++)
                kr[i] = *reinterpret_cast<const float4*>(
                    &K[(size_t)(n1 + lrow[i]) * DD + ld0[i]]);
            unsigned vbase = (unsigned)__cvta_generic_to_shared(Vnxt);
            #pragma unroll
            for (int i = 0; i < 8; i++)
                cp_async16(vbase + (unsigned)((lrow[i] * DD + ld0[i]) << 2),
                           &V[(size_t)(n1 + lrow[i]) * DD + ld0[i]]);
            cp_commit();
        }
        __syncthreads();   // Ks visible

        // ---- S = Q @ K^T : packed pairs along m ----
        ull s2[4][4];
        #pragma unroll
        for (int p = 0; p < 4; p++)
            #pragma unroll
            for (int j = 0; j < 4; j++) s2[p][j] = 0ULL;

        #pragma unroll 2
        for (int d4 = 0; d4 < 16; d4++) {
            const int sq0 = ((ty2 + 0) ^ d4) << 2;
            const int sq1 = ((ty2 + 1) ^ d4) << 2;
            const int sk  = (tx ^ d4) << 2;
            #pragma unroll
            for (int dd = 0; dd < 4; dd++) {
                const float* row = Qs + ((d4 << 2) + dd) * DD;
                const float* krow = Ks + ((d4 << 2) + dd) * DD;
                ulonglong2 qa = *reinterpret_cast<const ulonglong2*>(row + sq0);
                ulonglong2 qb = *reinterpret_cast<const ulonglong2*>(row + sq1);
                float4 kv = *reinterpret_cast<const float4*>(krow + sk);
                ull k0 = dup2(kv.x), k1 = dup2(kv.y), k2 = dup2(kv.z), k3 = dup2(kv.w);
                ull qp[4] = {qa.x, qa.y, qb.x, qb.y};
                #pragma unroll
                for (int p = 0; p < 4; p++) {
                    ffma2(s2[p][0], qp[p], k0);
                    ffma2(s2[p][1], qp[p], k1);
                    ffma2(s2[p][2], qp[p], k2);
                    ffma2(s2[p][3], qp[p], k3);
                }
            }
        }

        // ---- online softmax (unscaled) ----
        float s[8][4];
        #pragma unroll
        for (int p = 0; p < 4; p++)
            #pragma unroll
            for (int j = 0; j < 4; j++) unpack2(s2[p][j], s[2 * p][j], s[2 * p + 1][j]);

        float corr[8];
        #pragma unroll
        for (int m = 0; m < 8; m++) {
            float mx = fmaxf(fmaxf(s[m][0], s[m][1]), fmaxf(s[m][2], s[m][3]));
            #pragma unroll
            for (int o = 1; o < 16; o <<= 1)
                mx = fmaxf(mx, __shfl_xor_sync(0xffffffffu, mx, o, 16));
            float nm = fmaxf(rmax[m], mx);
            corr[m] = __expf(rmax[m] - nm);
            rmax[m] = nm;
            float ts = 0.f;
            #pragma unroll
            for (int j = 0; j < 4; j++) {
                float p = __expf(s[m][j] - nm);
                s[m][j] = p;
                ts += p;
            }
            #pragma unroll
            for (int o = 1; o < 16; o <<= 1)
                ts += __shfl_xor_sync(0xffffffffu, ts, o, 16);
            rsum[m] = rsum[m] * corr[m] + ts;
        }
        #pragma unroll
        for (int p = 0; p < 4; p++) {
            ull c2 = pack2(corr[2 * p], corr[2 * p + 1]);
            #pragma unroll
            for (int j = 0; j < 4; j++) acc[p][j] = mul2(acc[p][j], c2);
        }

        // ---- store P transposed: Ps[n][m], slot = (m>>2) ^ (n>>2) ----
        #pragma unroll
        for (int h = 0; h < 2; h++) {
            const int slot = ((ty2 + h) ^ tx) << 2;
            #pragma unroll
            for (int j = 0; j < 4; j++) {
                float4 pv = make_float4(s[4 * h + 0][j], s[4 * h + 1][j],
                                        s[4 * h + 2][j], s[4 * h + 3][j]);
                *reinterpret_cast<float4*>(&Ps[((tx << 2) + j) * DD + slot]) = pv;
            }
        }
        __syncthreads();   // Ps visible

        // ---- O += P @ V ----
        #pragma unroll 2
        for (int n4 = 0; n4 < 16; n4++) {
            const int sp0 = ((ty2 + 0) ^ n4) << 2;
            const int sp1 = ((ty2 + 1) ^ n4) << 2;
            #pragma unroll
            for (int nn = 0; nn < 4; nn++) {
                const int n = (n4 << 2) + nn;
                const float* prow = Ps + n * DD;
                ulonglong2 pa = *reinterpret_cast<const ulonglong2*>(prow + sp0);
                ulonglong2 pb = *reinterpret_cast<const ulonglong2*>(prow + sp1);
                float4 vv = *reinterpret_cast<const float4*>(Vcur + n * DD + (tx << 2));
                ull v0 = dup2(vv.x), v1 = dup2(vv.y), v2 = dup2(vv.z), v3 = dup2(vv.w);
                ull pp[4] = {pa.x, pa.y, pb.x, pb.y};
                #pragma unroll
                for (int p = 0; p < 4; p++) {
                    ffma2(acc[p][0], pp[p], v0);
                    ffma2(acc[p][1], pp[p], v1);
                    ffma2(acc[p][2], pp[p], v2);
                    ffma2(acc[p][3], pp[p], v3);
                }
            }
        }
    }

    // ---- epilogue: /rowsum, *1/sqrt(D)=0.125 ----
    #pragma unroll
    for (int p = 0; p < 4; p++) {
        float lo[4], hi[4];
        #pragma unroll
        for (int j = 0; j < 4; j++) unpack2(acc[p][j], lo[j], hi[j]);
        float sc0 = 0.125f / rsum[2 * p];
        float sc1 = 0.125f / rsum[2 * p + 1];
        int m = q0 + ty * 8 + 2 * p;
        size_t base = ((size_t)b * T_DIM + m) * DD + (tx << 2);
        *reinterpret_cast<float4*>(&out[base]) =
            make_float4(lo[0] * sc0, lo[1] * sc0, lo[2] * sc0, lo[3] * sc0);
        *reinterpret_cast<float4*>(&out[base + DD]) =
            make_float4(hi[0] * sc1, hi[1] * sc1, hi[2] * sc1, hi[3] * sc1);
    }
}

// ---------------------------------------------------------------------------
extern "C" void kernel_launch(void* const* d_in, const int* in_sizes, int n_in,
                              void* d_out, int out_size)
{
    const float* x  = (const float*)d_in[0];
    const float* Wq = (const float*)d_in[1];
    const float* Wk = (const float*)d_in[2];
    const float* Wv = (const float*)d_in[3];
    float* out = (float*)d_out;

    dim3 g1(M_ROWS / 128, 3);
    qkv_kernel<<<g1, 256>>>(x, Wq, Wk, Wv);

    const size_t smem = 20480 * sizeof(float);   // 81920 B
    cudaFuncSetAttribute(attn_kernel,
                         cudaFuncAttributeMaxDynamicSharedMemorySize, (int)smem);
    dim3 g2(T_DIM / 64, B_DIM);
    attn_kernel<<<g2, 128, smem>>>(out);
}

// round 5
// speedup vs baseline: 1.8200x; 1.8200x over previous
#include <cuda_runtime.h>
#include <cuda_bf16.h>
#include <cstdint>

#define E_DIM 1024
#define D_DIM 64
#define B_DIM 4
#define T_DIM 4096
#define M_ROWS (B_DIM * T_DIM)   // 16384

typedef unsigned long long ull;

// Device-global scratch (no runtime allocs).
__device__ float    g_v[M_ROWS * D_DIM];            // V fp32 [row][64]
__device__ unsigned g_qhi[M_ROWS * 32];             // Q bf16x2 [row][32]
__device__ unsigned g_qlo[M_ROWS * 32];
__device__ unsigned g_khi[M_ROWS * 32];             // K bf16x2 [row][32]
__device__ unsigned g_klo[M_ROWS * 32];
__device__ unsigned g_vthi[B_DIM * 64 * 2048];      // V^T bf16x2 [b][d][2048 seq-pairs]
__device__ unsigned g_vtlo[B_DIM * 64 * 2048];

// ---------------- helpers ----------------
__device__ __forceinline__ void ffma2(ull& d, ull a, ull b) {
    asm("fma.rn.f32x2 %0, %1, %2, %0;" : "+l"(d) : "l"(a), "l"(b));
}
__device__ __forceinline__ ull dup2(float x) {
    ull r; asm("mov.b64 %0, {%1, %1};" : "=l"(r) : "f"(x)); return r;
}
__device__ __forceinline__ void unpack2(ull v, float& lo, float& hi) {
    asm("mov.b64 {%0, %1}, %2;" : "=f"(lo), "=f"(hi) : "l"(v));
}
__device__ __forceinline__ void cp_async16(unsigned smem_addr, const void* gptr) {
    asm volatile("cp.async.ca.shared.global [%0], [%1], 16;" :: "r"(smem_addr), "l"(gptr));
}
__device__ __forceinline__ void cp_commit() { asm volatile("cp.async.commit_group;"); }
__device__ __forceinline__ void cp_wait0()  { asm volatile("cp.async.wait_group 0;"); }

// pack two f32 -> bf16x2 (lo -> bits[15:0], hi -> bits[31:16])
__device__ __forceinline__ unsigned packbf(float lo, float hi) {
    unsigned r;
    asm("cvt.rn.bf16x2.f32 %0, %1, %2;" : "=r"(r) : "f"(hi), "f"(lo));
    return r;
}
__device__ __forceinline__ float bflo(unsigned u) { return __uint_as_float(u << 16); }
__device__ __forceinline__ float bfhi(unsigned u) { return __uint_as_float(u & 0xffff0000u); }

// mma.sync m16n8k16 bf16 (row.col), f32 accumulate in-place
__device__ __forceinline__ void mma_bf16(float* d, const unsigned* a, const unsigned* b) {
    asm volatile(
        "mma.sync.aligned.m16n8k16.row.col.f32.bf16.bf16.f32 "
        "{%0,%1,%2,%3},{%4,%5,%6,%7},{%8,%9},{%0,%1,%2,%3};"
        : "+f"(d[0]), "+f"(d[1]), "+f"(d[2]), "+f"(d[3])
        : "r"(a[0]), "r"(a[1]), "r"(a[2]), "r"(a[3]), "r"(b[0]), "r"(b[1]));
}

// ---------------------------------------------------------------------------
// Kernel 1: QKV projection (FFMA2, proven). Epilogue writes:
//   blockIdx.y 0 -> Q bf16 hi/lo ; 1 -> K bf16 hi/lo ; 2 -> V fp32.
// ---------------------------------------------------------------------------
__global__ __launch_bounds__(256)
void qkv_kernel(const float* __restrict__ x,
                const float* __restrict__ Wq,
                const float* __restrict__ Wk,
                const float* __restrict__ Wv)
{
    constexpr int BM = 128, BK = 32, BN = 64;
    __shared__ float As[BK * BM];   // transposed [k][m], swizzled
    __shared__ float Bs[BK * BN];   // natural [k][n]

    const int tid = threadIdx.x;
    const int ty  = tid >> 4;
    const int tx  = tid & 15;
    const int ty2 = ty << 1;
    const int m0  = blockIdx.x * BM;

    const float* W = (blockIdx.y == 0) ? Wq : (blockIdx.y == 1) ? Wk : Wv;

    ull acc[4][4];
    #pragma unroll
    for (int p = 0; p < 4; p++)
        #pragma unroll
        for (int j = 0; j < 4; j++) acc[p][j] = 0ULL;

    float4 xr[4], wr[2];
    #pragma unroll
    for (int i = 0; i < 4; i++) {
        int f = tid + 256 * i;
        int m = f >> 3;
        int kc = (f & 7) << 2;
        xr[i] = *reinterpret_cast<const float4*>(&x[(size_t)(m0 + m) * E_DIM + kc]);
    }
    #pragma unroll
    for (int i = 0; i < 2; i++) {
        int f = tid + 256 * i;
        int r = f >> 4;
        int c4 = (f & 15) << 2;
        wr[i] = *reinterpret_cast<const float4*>(&W[(size_t)r * BN + c4]);
    }

    for (int k0 = 0; k0 < E_DIM; k0 += BK) {
        __syncthreads();
        #pragma unroll
        for (int i = 0; i < 4; i++) {
            int f = tid + 256 * i;
            int m = f >> 3;
            int kc = (f & 7) << 2;
            int slot = ((m >> 2) ^ (f & 7)) << 2;
            int ml = m & 3;
            As[(kc + 0) * BM + slot + ml] = xr[i].x;
            As[(kc + 1) * BM + slot + ml] = xr[i].y;
            As[(kc + 2) * BM + slot + ml] = xr[i].z;
            As[(kc + 3) * BM + slot + ml] = xr[i].w;
        }
        #pragma unroll
        for (int i = 0; i < 2; i++) {
            int f = tid + 256 * i;
            int r = f >> 4;
            int c4 = (f & 15) << 2;
            *reinterpret_cast<float4*>(&Bs[r * BN + c4]) = wr[i];
        }
        if (k0 + BK < E_DIM) {
            #pragma unroll
            for (int i = 0; i < 4; i++) {
                int f = tid + 256 * i;
                int m = f >> 3;
                int kc = (f & 7) << 2;
                xr[i] = *reinterpret_cast<const float4*>(
                    &x[(size_t)(m0 + m) * E_DIM + k0 + BK + kc]);
            }
            #pragma unroll
            for (int i = 0; i < 2; i++) {
                int f = tid + 256 * i;
                int r = f >> 4;
                int c4 = (f & 15) << 2;
                wr[i] = *reinterpret_cast<const float4*>(
                    &W[(size_t)(k0 + BK + r) * BN + c4]);
            }
        }
        __syncthreads();

        #pragma unroll 2
        for (int k4 = 0; k4 < BK / 4; k4++) {
            const int g = k4 & 7;
            const int sa0 = ((ty2 + 0) ^ g) << 2;
            const int sa1 = ((ty2 + 1) ^ g) << 2;
            #pragma unroll
            for (int kk = 0; kk < 4; kk++) {
                const int k = (k4 << 2) + kk;
                const float* arow = As + k * BM;
                ulonglong2 a01 = *reinterpret_cast<const ulonglong2*>(arow + sa0);
                ulonglong2 a23 = *reinterpret_cast<const ulonglong2*>(arow + sa1);
                float4 bv = *reinterpret_cast<const float4*>(&Bs[k * BN + (tx << 2)]);
                ull b0 = dup2(bv.x), b1 = dup2(bv.y), b2 = dup2(bv.z), b3 = dup2(bv.w);
                ull ap[4] = {a01.x, a01.y, a23.x, a23.y};
                #pragma unroll
                for (int p = 0; p < 4; p++) {
                    ffma2(acc[p][0], ap[p], b0);
                    ffma2(acc[p][1], ap[p], b1);
                    ffma2(acc[p][2], ap[p], b2);
                    ffma2(acc[p][3], ap[p], b3);
                }
            }
        }
    }

    // ---- epilogue ----
    if (blockIdx.y == 2) {
        #pragma unroll
        for (int p = 0; p < 4; p++) {
            float lo[4], hi[4];
            #pragma unroll
            for (int j = 0; j < 4; j++) unpack2(acc[p][j], lo[j], hi[j]);
            size_t r0 = (size_t)(m0 + ty * 8 + 2 * p) * D_DIM + (tx << 2);
            *reinterpret_cast<float4*>(&g_v[r0])         = make_float4(lo[0], lo[1], lo[2], lo[3]);
            *reinterpret_cast<float4*>(&g_v[r0 + D_DIM]) = make_float4(hi[0], hi[1], hi[2], hi[3]);
        }
    } else {
        unsigned* Ghi = (blockIdx.y == 0) ? g_qhi : g_khi;
        unsigned* Glo = (blockIdx.y == 0) ? g_qlo : g_klo;
        #pragma unroll
        for (int p = 0; p < 4; p++) {
            float lo[4], hi[4];
            #pragma unroll
            for (int j = 0; j < 4; j++) unpack2(acc[p][j], lo[j], hi[j]);
            int rowe = m0 + ty * 8 + 2 * p;
            // even row
            unsigned h0 = packbf(lo[0], lo[1]);
            unsigned h1 = packbf(lo[2], lo[3]);
            unsigned l0 = packbf(lo[0] - bflo(h0), lo[1] - bfhi(h0));
            unsigned l1 = packbf(lo[2] - bflo(h1), lo[3] - bfhi(h1));
            int idx = rowe * 32 + tx * 2;
            Ghi[idx] = h0; Ghi[idx + 1] = h1;
            Glo[idx] = l0; Glo[idx + 1] = l1;
            // odd row
            unsigned h2 = packbf(hi[0], hi[1]);
            unsigned h3 = packbf(hi[2], hi[3]);
            unsigned l2 = packbf(hi[0] - bflo(h2), hi[1] - bfhi(h2));
            unsigned l3 = packbf(hi[2] - bflo(h3), hi[3] - bfhi(h3));
            idx += 32;
            Ghi[idx] = h2; Ghi[idx + 1] = h3;
            Glo[idx] = l2; Glo[idx + 1] = l3;
        }
    }
}

// ---------------------------------------------------------------------------
// Kernel 1b: V^T bf16 hi/lo.  g_vt*[b][d][sp] = pack(V[b][2sp][d], V[b][2sp+1][d])
// ---------------------------------------------------------------------------
__global__ __launch_bounds__(256)
void vt_kernel()
{
    int idx = blockIdx.x * 256 + threadIdx.x;     // < B*64*2048 = 524288
    int b  = idx >> 17;
    int d  = (idx >> 11) & 63;
    int sp = idx & 2047;
    const float* vp = g_v + ((size_t)b * T_DIM + 2 * sp) * D_DIM + d;
    float v0 = vp[0], v1 = vp[D_DIM];
    unsigned h = packbf(v0, v1);
    unsigned l = packbf(v0 - bflo(h), v1 - bfhi(h));
    g_vthi[idx] = h;
    g_vtlo[idx] = l;
}

// ---------------------------------------------------------------------------
// Kernel 2: flash attention on mma.sync (bf16 3-term split, fp32 accum).
// CTA: 256 thr (8 warps), BM=128 q rows (warp w -> rows w*16..+15), BN=64.
// smem per buffer: Khi,Klo [64 n][36 u32 d-pairs], Vthi,Vtlo [64 d][36 u32 seq-pairs]
//   (stride 36 u32 -> B-fragment LDS conflict-free). Double buffered: 73728 B.
// P never touches smem: S C-fragments == PV A-fragments layout.
// ---------------------------------------------------------------------------
__global__ __launch_bounds__(256)
void attn_kernel(float* __restrict__ out)
{
    constexpr int NT = T_DIM / 64;       // 64 kv tiles
    extern __shared__ unsigned sm32[];

    const int tid = threadIdx.x;
    const int w   = tid >> 5;
    const int l   = tid & 31;
    const int lq  = l >> 2;              // groupID  (0..7)
    const int lr  = l & 3;               // thread-in-group (0..3)
    const int b   = blockIdx.y;
    const int q0  = blockIdx.x * 128;    // q row base within batch

    // ---- persistent Q fragments (hi/lo) ----
    unsigned qh[4][4], ql[4][4];
    {
        const unsigned* Qh = g_qhi + ((size_t)b * T_DIM + q0 + w * 16) * 32;
        const unsigned* Ql = g_qlo + ((size_t)b * T_DIM + q0 + w * 16) * 32;
        #pragma unroll
        for (int s = 0; s < 4; s++) {
            int c0 = 8 * s + lr, c1 = 8 * s + 4 + lr;
            qh[s][0] = Qh[lq * 32 + c0];       qh[s][1] = Qh[(lq + 8) * 32 + c0];
            qh[s][2] = Qh[lq * 32 + c1];       qh[s][3] = Qh[(lq + 8) * 32 + c1];
            ql[s][0] = Ql[lq * 32 + c0];       ql[s][1] = Ql[(lq + 8) * 32 + c0];
            ql[s][2] = Ql[lq * 32 + c1];       ql[s][3] = Ql[(lq + 8) * 32 + c1];
        }
    }

    // ---- cp.async loader geometry: 8 granules/thread, 4 arrays x 64 rows x 8 ----
    const unsigned sbase = (unsigned)__cvta_generic_to_shared(sm32);
    const unsigned* srcp[8];
    unsigned dstoff[8];   // u32 units within one buffer
    unsigned step[8];
    #pragma unroll
    for (int i = 0; i < 8; i++) {
        int g   = tid + 256 * i;         // 0..2047
        int arr = g >> 9;
        int row = (g >> 3) & 63;
        int c   = g & 7;
        dstoff[i] = arr * 2304 + row * 36 + c * 4;
        if (arr == 0)      { srcp[i] = g_khi  + ((size_t)b * T_DIM + row) * 32 + c * 4; step[i] = 2048; }
        else if (arr == 1) { srcp[i] = g_klo  + ((size_t)b * T_DIM + row) * 32 + c * 4; step[i] = 2048; }
        else if (arr == 2) { srcp[i] = g_vthi + (size_t)b * 131072 + row * 2048 + c * 4; step[i] = 32; }
        else               { srcp[i] = g_vtlo + (size_t)b * 131072 + row * 2048 + c * 4; step[i] = 32; }
    }

    // prologue: issue tile 0 into buffer 0
    #pragma unroll
    for (int i = 0; i < 8; i++) {
        cp_async16(sbase + (dstoff[i] << 2), srcp[i]);
        srcp[i] += step[i];
    }
    cp_commit();

    // ---- state ----
    float acc[8][4];
    #pragma unroll
    for (int t = 0; t < 8; t++)
        #pragma unroll
        for (int j = 0; j < 4; j++) acc[t][j] = 0.f;
    float rmax0 = -1e30f, rmax1 = -1e30f, rsum0 = 0.f, rsum1 = 0.f;

    for (int t = 0; t < NT; t++) {
        cp_wait0();
        __syncthreads();     // tile t ready; all warps done with the other buffer

        if (t + 1 < NT) {
            unsigned boff = sbase + (((t + 1) & 1) ? 36864u : 0u);
            #pragma unroll
            for (int i = 0; i < 8; i++) {
                cp_async16(boff + (dstoff[i] << 2), srcp[i]);
                srcp[i] += step[i];
            }
            cp_commit();
        }

        const unsigned* cur = sm32 + (t & 1) * 9216;
        const unsigned* kh = cur;
        const unsigned* kl = cur + 2304;
        const unsigned* vh = cur + 4608;
        const unsigned* vl = cur + 6912;

        // ---- S = Q K^T (3-pass split) ----
        float sf[8][4];
        #pragma unroll
        for (int t8 = 0; t8 < 8; t8++)
            #pragma unroll
            for (int j = 0; j < 4; j++) sf[t8][j] = 0.f;

        #pragma unroll
        for (int t8 = 0; t8 < 8; t8++) {
            const int rb = (t8 * 8 + lq) * 36;
            unsigned bh[4][2], bl[4][2];
            #pragma unroll
            for (int s = 0; s < 4; s++) {
                bh[s][0] = kh[rb + 8 * s + lr];
                bh[s][1] = kh[rb + 8 * s + 4 + lr];
                bl[s][0] = kl[rb + 8 * s + lr];
                bl[s][1] = kl[rb + 8 * s + 4 + lr];
            }
            #pragma unroll
            for (int s = 0; s < 4; s++) {
                mma_bf16(sf[t8], qh[s], bh[s]);
                mma_bf16(sf[t8], qh[s], bl[s]);
                mma_bf16(sf[t8], ql[s], bh[s]);
            }
        }

        // ---- online softmax (rows r0=lq, r1=lq+8; reduce over 4-lane group) ----
        float mx0 = sf[0][0], mx1 = sf[0][2];
        #pragma unroll
        for (int t8 = 0; t8 < 8; t8++) {
            mx0 = fmaxf(mx0, fmaxf(sf[t8][0], sf[t8][1]));
            mx1 = fmaxf(mx1, fmaxf(sf[t8][2], sf[t8][3]));
        }
        mx0 = fmaxf(mx0, __shfl_xor_sync(0xffffffffu, mx0, 1));
        mx0 = fmaxf(mx0, __shfl_xor_sync(0xffffffffu, mx0, 2));
        mx1 = fmaxf(mx1, __shfl_xor_sync(0xffffffffu, mx1, 1));
        mx1 = fmaxf(mx1, __shfl_xor_sync(0xffffffffu, mx1, 2));

        float nm0 = fmaxf(rmax0, mx0), nm1 = fmaxf(rmax1, mx1);
        float corr0 = __expf(rmax0 - nm0), corr1 = __expf(rmax1 - nm1);
        rmax0 = nm0; rmax1 = nm1;

        float ts0 = 0.f, ts1 = 0.f;
        #pragma unroll
        for (int t8 = 0; t8 < 8; t8++) {
            sf[t8][0] = __expf(sf[t8][0] - nm0);
            sf[t8][1] = __expf(sf[t8][1] - nm0);
            sf[t8][2] = __expf(sf[t8][2] - nm1);
            sf[t8][3] = __expf(sf[t8][3] - nm1);
            ts0 += sf[t8][0] + sf[t8][1];
            ts1 += sf[t8][2] + sf[t8][3];
        }
        ts0 += __shfl_xor_sync(0xffffffffu, ts0, 1);
        ts0 += __shfl_xor_sync(0xffffffffu, ts0, 2);
        ts1 += __shfl_xor_sync(0xffffffffu, ts1, 1);
        ts1 += __shfl_xor_sync(0xffffffffu, ts1, 2);
        rsum0 = rsum0 * corr0 + ts0;
        rsum1 = rsum1 * corr1 + ts1;

        #pragma unroll
        for (int t8 = 0; t8 < 8; t8++) {
            acc[t8][0] *= corr0; acc[t8][1] *= corr0;
            acc[t8][2] *= corr1; acc[t8][3] *= corr1;
        }

        // ---- P fragments (hi + residual lo), straight from sf regs ----
        unsigned pah[4][4], pal[4][4];
        #pragma unroll
        for (int s = 0; s < 4; s++) {
            const float* e = sf[2 * s];
            const float* o = sf[2 * s + 1];
            unsigned a0 = packbf(e[0], e[1]);
            unsigned a1 = packbf(e[2], e[3]);
            unsigned a2 = packbf(o[0], o[1]);
            unsigned a3 = packbf(o[2], o[3]);
            pah[s][0] = a0; pah[s][1] = a1; pah[s][2] = a2; pah[s][3] = a3;
            pal[s][0] = packbf(e[0] - bflo(a0), e[1] - bfhi(a0));
            pal[s][1] = packbf(e[2] - bflo(a1), e[3] - bfhi(a1));
            pal[s][2] = packbf(o[0] - bflo(a2), o[1] - bfhi(a2));
            pal[s][3] = packbf(o[2] - bflo(a3), o[3] - bfhi(a3));
        }

        // ---- O += P V (3-pass split) ----
        #pragma unroll
        for (int t8 = 0; t8 < 8; t8++) {
            const int rb = (t8 * 8 + lq) * 36;
            unsigned bh[4][2], bl[4][2];
            #pragma unroll
            for (int s = 0; s < 4; s++) {
                bh[s][0] = vh[rb + 8 * s + lr];
                bh[s][1] = vh[rb + 8 * s + 4 + lr];
                bl[s][0] = vl[rb + 8 * s + lr];
                bl[s][1] = vl[rb + 8 * s + 4 + lr];
            }
            #pragma unroll
            for (int s = 0; s < 4; s++) {
                mma_bf16(acc[t8], pah[s], bh[s]);
                mma_bf16(acc[t8], pah[s], bl[s]);
                mma_bf16(acc[t8], pal[s], bh[s]);
            }
        }
    }

    // ---- epilogue ----
    float sc0 = 0.125f / rsum0;
    float sc1 = 0.125f / rsum1;
    int mr0 = q0 + w * 16 + lq;
    size_t base0 = ((size_t)b * T_DIM + mr0) * D_DIM;
    size_t base1 = base0 + 8 * D_DIM;
    #pragma unroll
    for (int t8 = 0; t8 < 8; t8++) {
        int col = 8 * t8 + 2 * lr;
        *reinterpret_cast<float2*>(&out[base0 + col]) =
            make_float2(acc[t8][0] * sc0, acc[t8][1] * sc0);
        *reinterpret_cast<float2*>(&out[base1 + col]) =
            make_float2(acc[t8][2] * sc1, acc[t8][3] * sc1);
    }
}

// ---------------------------------------------------------------------------
extern "C" void kernel_launch(void* const* d_in, const int* in_sizes, int n_in,
                              void* d_out, int out_size)
{
    const float* x  = (const float*)d_in[0];
    const float* Wq = (const float*)d_in[1];
    const float* Wk = (const float*)d_in[2];
    const float* Wv = (const float*)d_in[3];
    float* out = (float*)d_out;

    dim3 g1(M_ROWS / 128, 3);
    qkv_kernel<<<g1, 256>>>(x, Wq, Wk, Wv);

    vt_kernel<<<(B_DIM * 64 * 2048) / 256, 256>>>();

    const int smem = 73728;
    cudaFuncSetAttribute(attn_kernel,
                         cudaFuncAttributeMaxDynamicSharedMemorySize, smem);
    dim3 g2(T_DIM / 128, B_DIM);
    attn_kernel<<<g2, 256, smem>>>(out);
}

// round 6
// speedup vs baseline: 2.2571x; 1.2402x over previous
#include <cuda_runtime.h>
#include <cuda_bf16.h>
#include <cstdint>

#define E_DIM 1024
#define D_DIM 64
#define B_DIM 4
#define T_DIM 4096
#define M_ROWS (B_DIM * T_DIM)   // 16384

typedef unsigned long long ull;

// Device-global scratch (no runtime allocs).
__device__ float    g_v[M_ROWS * D_DIM];            // V fp32 [row][64]
__device__ unsigned g_qhi[M_ROWS * 32];             // Q bf16x2 [row][32 pairs]
__device__ unsigned g_qlo[M_ROWS * 32];
__device__ unsigned g_khi[M_ROWS * 32];             // K bf16x2 [row][32 pairs]
__device__ unsigned g_klo[M_ROWS * 32];
__device__ unsigned g_vthi[B_DIM * 64 * 2048];      // V^T bf16x2 [b][d][2048 seq-pairs]
__device__ unsigned g_vtlo[B_DIM * 64 * 2048];
__device__ unsigned g_wthi[3 * 64 * 512];           // W^T bf16x2 [j][d][512 e-pairs]
__device__ unsigned g_wtlo[3 * 64 * 512];

// ---------------- helpers ----------------
__device__ __forceinline__ void cp_async16(unsigned smem_addr, const void* gptr) {
    asm volatile("cp.async.ca.shared.global [%0], [%1], 16;" :: "r"(smem_addr), "l"(gptr));
}
__device__ __forceinline__ void cp_commit() { asm volatile("cp.async.commit_group;"); }
__device__ __forceinline__ void cp_wait0()  { asm volatile("cp.async.wait_group 0;"); }
__device__ __forceinline__ void cp_wait1()  { asm volatile("cp.async.wait_group 1;"); }

// pack two f32 -> bf16x2 (first arg -> bits[15:0], second -> bits[31:16])
__device__ __forceinline__ unsigned packbf(float lo, float hi) {
    unsigned r;
    asm("cvt.rn.bf16x2.f32 %0, %1, %2;" : "=r"(r) : "f"(hi), "f"(lo));
    return r;
}
__device__ __forceinline__ float bflo(unsigned u) { return __uint_as_float(u << 16); }
__device__ __forceinline__ float bfhi(unsigned u) { return __uint_as_float(u & 0xffff0000u); }

// mma.sync m16n8k16 bf16 (row.col), f32 accumulate in-place
__device__ __forceinline__ void mma_bf16(float* d, const unsigned* a, const unsigned* b) {
    asm volatile(
        "mma.sync.aligned.m16n8k16.row.col.f32.bf16.bf16.f32 "
        "{%0,%1,%2,%3},{%4,%5,%6,%7},{%8,%9},{%0,%1,%2,%3};"
        : "+f"(d[0]), "+f"(d[1]), "+f"(d[2]), "+f"(d[3])
        : "r"(a[0]), "r"(a[1]), "r"(a[2]), "r"(a[3]), "r"(b[0]), "r"(b[1]));
}

// ---------------------------------------------------------------------------
// Kernel 0: W^T bf16 hi/lo split.  g_wt*[(j*64+d)*512 + p] = pack(W[2p][d], W[2p+1][d])
// ---------------------------------------------------------------------------
__global__ __launch_bounds__(256)
void split_w_kernel(const float* __restrict__ Wq,
                    const float* __restrict__ Wk,
                    const float* __restrict__ Wv)
{
    int idx = blockIdx.x * 256 + threadIdx.x;   // < 3*64*512 = 98304
    if (idx >= 3 * 64 * 512) return;
    int j = idx >> 15;
    int d = (idx >> 9) & 63;
    int p = idx & 511;
    const float* W = (j == 0) ? Wq : (j == 1) ? Wk : Wv;
    float w0 = W[(size_t)(2 * p) * D_DIM + d];
    float w1 = W[(size_t)(2 * p + 1) * D_DIM + d];
    unsigned h = packbf(w0, w1);
    unsigned l = packbf(w0 - bflo(h), w1 - bfhi(h));
    g_wthi[idx] = h;
    g_wtlo[idx] = l;
}

// ---------------------------------------------------------------------------
// Kernel 1: QKV projection on mma.sync (bf16 3-term split).
// Grid (3, 128): blockIdx.x = j (0=Q,1=K,2=V), blockIdx.y = 128-row slab.
// 256 thr / 8 warps; warp w -> rows 16w..16w+15. N=64 (8 n-tiles), BK=32.
// x fp32 loaded+converted in-kernel; W^T hi/lo via cp.async.
// Smem tiles: [rows][16 pairs] stride 20 u32 -> all fragment LDS conflict-free.
// Layout (u32): XH 0/2560, XL 5120/7680, WH 10240/11520, WL 12800/14080.
// ---------------------------------------------------------------------------
#define QKV_SMEM_BYTES (15360 * 4)

__global__ __launch_bounds__(256, 2)
void qkv_mma_kernel(const float* __restrict__ x)
{
    extern __shared__ unsigned qsm[];
    const int tid = threadIdx.x;
    const int w   = tid >> 5;
    const int l   = tid & 31;
    const int lq  = l >> 2;
    const int lr  = l & 3;
    const int j   = blockIdx.x;
    const int m0  = blockIdx.y * 128;

    const unsigned sbase = (unsigned)__cvta_generic_to_shared(qsm);
    const unsigned* WHsrc = g_wthi + (size_t)j * 32768;
    const unsigned* WLsrc = g_wtlo + (size_t)j * 32768;
    const int wrow = (tid & 255) >> 2;   // 0..63
    const int wpg  = tid & 3;            // pair-group of 4

    // prologue: x chunk 0 -> regs; W chunk 0 -> cp.async buf 0
    float4 xr[4];
    #pragma unroll
    for (int i = 0; i < 4; i++) {
        int g = tid + 256 * i;
        int row = g >> 3, c4 = g & 7;
        xr[i] = *reinterpret_cast<const float4*>(&x[(size_t)(m0 + row) * E_DIM + 4 * c4]);
    }
    cp_async16(sbase + (10240u + wrow * 20 + 4 * wpg) * 4, WHsrc + wrow * 512 + 4 * wpg);
    cp_async16(sbase + (12800u + wrow * 20 + 4 * wpg) * 4, WLsrc + wrow * 512 + 4 * wpg);
    cp_commit();

    float acc[8][4];
    #pragma unroll
    for (int nt = 0; nt < 8; nt++)
        #pragma unroll
        for (int i = 0; i < 4; i++) acc[nt][i] = 0.f;

    for (int t = 0; t < 32; t++) {
        const int c = t & 1;
        const unsigned xh = c ? 2560u : 0u;
        const unsigned xl = c ? 7680u : 5120u;
        const unsigned wh = c ? 11520u : 10240u;
        const unsigned wl = c ? 14080u : 12800u;

        __syncthreads();   // buf c free (compute t-1 done)

        // store x(t) bf16 hi/lo into buf c
        #pragma unroll
        for (int i = 0; i < 4; i++) {
            int g = tid + 256 * i;
            int row = g >> 3, c4 = g & 7;
            unsigned h0 = packbf(xr[i].x, xr[i].y);
            unsigned h1 = packbf(xr[i].z, xr[i].w);
            unsigned l0 = packbf(xr[i].x - bflo(h0), xr[i].y - bfhi(h0));
            unsigned l1 = packbf(xr[i].z - bflo(h1), xr[i].w - bfhi(h1));
            unsigned wd = row * 20 + 2 * c4;
            *reinterpret_cast<uint2*>(&qsm[xh + wd]) = make_uint2(h0, h1);
            *reinterpret_cast<uint2*>(&qsm[xl + wd]) = make_uint2(l0, l1);
        }
        // prefetch next chunk
        if (t + 1 < 32) {
            #pragma unroll
            for (int i = 0; i < 4; i++) {
                int g = tid + 256 * i;
                int row = g >> 3, c4 = g & 7;
                xr[i] = *reinterpret_cast<const float4*>(
                    &x[(size_t)(m0 + row) * E_DIM + (t + 1) * 32 + 4 * c4]);
            }
            const unsigned whn = c ? 10240u : 11520u;
            const unsigned wln = c ? 12800u : 14080u;
            cp_async16(sbase + (whn + wrow * 20 + 4 * wpg) * 4,
                       WHsrc + wrow * 512 + (t + 1) * 16 + 4 * wpg);
            cp_async16(sbase + (wln + wrow * 20 + 4 * wpg) * 4,
                       WLsrc + wrow * 512 + (t + 1) * 16 + 4 * wpg);
            cp_commit();
            cp_wait1();    // W(t) complete, W(t+1) in flight
        } else {
            cp_wait0();
        }
        __syncthreads();   // x(t) stores + W(t) visible

        // compute chunk t: 2 k16-steps
        const int ar = 16 * w + lq;
        #pragma unroll
        for (int s = 0; s < 2; s++) {
            const int ab = ar * 20 + 8 * s + lr;
            unsigned ah[4], al[4];
            ah[0] = qsm[xh + ab];       ah[1] = qsm[xh + ab + 160];
            ah[2] = qsm[xh + ab + 4];   ah[3] = qsm[xh + ab + 164];
            al[0] = qsm[xl + ab];       al[1] = qsm[xl + ab + 160];
            al[2] = qsm[xl + ab + 4];   al[3] = qsm[xl + ab + 164];
            #pragma unroll
            for (int nt = 0; nt < 8; nt++) {
                const int bb = (8 * nt + lq) * 20 + 8 * s + lr;
                unsigned bh[2] = { qsm[wh + bb], qsm[wh + bb + 4] };
                unsigned bl[2] = { qsm[wl + bb], qsm[wl + bb + 4] };
                mma_bf16(acc[nt], ah, bh);
                mma_bf16(acc[nt], ah, bl);
                mma_bf16(acc[nt], al, bh);
            }
        }
    }

    // epilogue
    const int row = m0 + 16 * w + lq;
    if (j == 2) {
        #pragma unroll
        for (int nt = 0; nt < 8; nt++) {
            *reinterpret_cast<float2*>(&g_v[(size_t)row * 64 + 8 * nt + 2 * lr]) =
                make_float2(acc[nt][0], acc[nt][1]);
            *reinterpret_cast<float2*>(&g_v[(size_t)(row + 8) * 64 + 8 * nt + 2 * lr]) =
                make_float2(acc[nt][2], acc[nt][3]);
        }
    } else {
        unsigned* Gh = j ? g_khi : g_qhi;
        unsigned* Gl = j ? g_klo : g_qlo;
        #pragma unroll
        for (int nt = 0; nt < 8; nt++) {
            unsigned h0 = packbf(acc[nt][0], acc[nt][1]);
            unsigned l0 = packbf(acc[nt][0] - bflo(h0), acc[nt][1] - bfhi(h0));
            Gh[(size_t)row * 32 + 4 * nt + lr] = h0;
            Gl[(size_t)row * 32 + 4 * nt + lr] = l0;
            unsigned h1 = packbf(acc[nt][2], acc[nt][3]);
            unsigned l1 = packbf(acc[nt][2] - bflo(h1), acc[nt][3] - bfhi(h1));
            Gh[(size_t)(row + 8) * 32 + 4 * nt + lr] = h1;
            Gl[(size_t)(row + 8) * 32 + 4 * nt + lr] = l1;
        }
    }
}

// ---------------------------------------------------------------------------
// Kernel 1b: V^T bf16 hi/lo.  g_vt*[b][d][sp] = pack(V[b][2sp][d], V[b][2sp+1][d])
// ---------------------------------------------------------------------------
__global__ __launch_bounds__(256)
void vt_kernel()
{
    int idx = blockIdx.x * 256 + threadIdx.x;     // < B*64*2048 = 524288
    int b  = idx >> 17;
    int d  = (idx >> 11) & 63;
    int sp = idx & 2047;
    const float* vp = g_v + ((size_t)b * T_DIM + 2 * sp) * D_DIM + d;
    float v0 = vp[0], v1 = vp[D_DIM];
    unsigned h = packbf(v0, v1);
    unsigned l = packbf(v0 - bflo(h), v1 - bfhi(h));
    g_vthi[idx] = h;
    g_vtlo[idx] = l;
}

// ---------------------------------------------------------------------------
// Kernel 2: flash attention on mma.sync (bf16 3-term split, fp32 accum).
// (Unchanged from round 5 — proven at ~165us, rel_err 1.7e-5.)
// ---------------------------------------------------------------------------
__global__ __launch_bounds__(256)
void attn_kernel(float* __restrict__ out)
{
    constexpr int NT = T_DIM / 64;
    extern __shared__ unsigned sm32[];

    const int tid = threadIdx.x;
    const int w   = tid >> 5;
    const int l   = tid & 31;
    const int lq  = l >> 2;
    const int lr  = l & 3;
    const int b   = blockIdx.y;
    const int q0  = blockIdx.x * 128;

    unsigned qh[4][4], ql[4][4];
    {
        const unsigned* Qh = g_qhi + ((size_t)b * T_DIM + q0 + w * 16) * 32;
        const unsigned* Ql = g_qlo + ((size_t)b * T_DIM + q0 + w * 16) * 32;
        #pragma unroll
        for (int s = 0; s < 4; s++) {
            int c0 = 8 * s + lr, c1 = 8 * s + 4 + lr;
            qh[s][0] = Qh[lq * 32 + c0];       qh[s][1] = Qh[(lq + 8) * 32 + c0];
            qh[s][2] = Qh[lq * 32 + c1];       qh[s][3] = Qh[(lq + 8) * 32 + c1];
            ql[s][0] = Ql[lq * 32 + c0];       ql[s][1] = Ql[(lq + 8) * 32 + c0];
            ql[s][2] = Ql[lq * 32 + c1];       ql[s][3] = Ql[(lq + 8) * 32 + c1];
        }
    }

    const unsigned sbase = (unsigned)__cvta_generic_to_shared(sm32);
    const unsigned* srcp[8];
    unsigned dstoff[8];
    unsigned step[8];
    #pragma unroll
    for (int i = 0; i < 8; i++) {
        int g   = tid + 256 * i;
        int arr = g >> 9;
        int row = (g >> 3) & 63;
        int c   = g & 7;
        dstoff[i] = arr * 2304 + row * 36 + c * 4;
        if (arr == 0)      { srcp[i] = g_khi  + ((size_t)b * T_DIM + row) * 32 + c * 4; step[i] = 2048; }
        else if (arr == 1) { srcp[i] = g_klo  + ((size_t)b * T_DIM + row) * 32 + c * 4; step[i] = 2048; }
        else if (arr == 2) { srcp[i] = g_vthi + (size_t)b * 131072 + row * 2048 + c * 4; step[i] = 32; }
        else               { srcp[i] = g_vtlo + (size_t)b * 131072 + row * 2048 + c * 4; step[i] = 32; }
    }

    #pragma unroll
    for (int i = 0; i < 8; i++) {
        cp_async16(sbase + (dstoff[i] << 2), srcp[i]);
        srcp[i] += step[i];
    }
    cp_commit();

    float acc[8][4];
    #pragma unroll
    for (int t = 0; t < 8; t++)
        #pragma unroll
        for (int j = 0; j < 4; j++) acc[t][j] = 0.f;
    float rmax0 = -1e30f, rmax1 = -1e30f, rsum0 = 0.f, rsum1 = 0.f;

    for (int t = 0; t < NT; t++) {
        cp_wait0();
        __syncthreads();

        if (t + 1 < NT) {
            unsigned boff = sbase + (((t + 1) & 1) ? 36864u : 0u);
            #pragma unroll
            for (int i = 0; i < 8; i++) {
                cp_async16(boff + (dstoff[i] << 2), srcp[i]);
                srcp[i] += step[i];
            }
            cp_commit();
        }

        const unsigned* cur = sm32 + (t & 1) * 9216;
        const unsigned* kh = cur;
        const unsigned* kl = cur + 2304;
        const unsigned* vh = cur + 4608;
        const unsigned* vl = cur + 6912;

        float sf[8][4];
        #pragma unroll
        for (int t8 = 0; t8 < 8; t8++)
            #pragma unroll
            for (int j = 0; j < 4; j++) sf[t8][j] = 0.f;

        #pragma unroll
        for (int t8 = 0; t8 < 8; t8++) {
            const int rb = (t8 * 8 + lq) * 36;
            unsigned bh[4][2], bl[4][2];
            #pragma unroll
            for (int s = 0; s < 4; s++) {
                bh[s][0] = kh[rb + 8 * s + lr];
                bh[s][1] = kh[rb + 8 * s + 4 + lr];
                bl[s][0] = kl[rb + 8 * s + lr];
                bl[s][1] = kl[rb + 8 * s + 4 + lr];
            }
            #pragma unroll
            for (int s = 0; s < 4; s++) {
                mma_bf16(sf[t8], qh[s], bh[s]);
                mma_bf16(sf[t8], qh[s], bl[s]);
                mma_bf16(sf[t8], ql[s], bh[s]);
            }
        }

        float mx0 = sf[0][0], mx1 = sf[0][2];
        #pragma unroll
        for (int t8 = 0; t8 < 8; t8++) {
            mx0 = fmaxf(mx0, fmaxf(sf[t8][0], sf[t8][1]));
            mx1 = fmaxf(mx1, fmaxf(sf[t8][2], sf[t8][3]));
        }
        mx0 = fmaxf(mx0, __shfl_xor_sync(0xffffffffu, mx0, 1));
        mx0 = fmaxf(mx0, __shfl_xor_sync(0xffffffffu, mx0, 2));
        mx1 = fmaxf(mx1, __shfl_xor_sync(0xffffffffu, mx1, 1));
        mx1 = fmaxf(mx1, __shfl_xor_sync(0xffffffffu, mx1, 2));

        float nm0 = fmaxf(rmax0, mx0), nm1 = fmaxf(rmax1, mx1);
        float corr0 = __expf(rmax0 - nm0), corr1 = __expf(rmax1 - nm1);
        rmax0 = nm0; rmax1 = nm1;

        float ts0 = 0.f, ts1 = 0.f;
        #pragma unroll
        for (int t8 = 0; t8 < 8; t8++) {
            sf[t8][0] = __expf(sf[t8][0] - nm0);
            sf[t8][1] = __expf(sf[t8][1] - nm0);
            sf[t8][2] = __expf(sf[t8][2] - nm1);
            sf[t8][3] = __expf(sf[t8][3] - nm1);
            ts0 += sf[t8][0] + sf[t8][1];
            ts1 += sf[t8][2] + sf[t8][3];
        }
        ts0 += __shfl_xor_sync(0xffffffffu, ts0, 1);
        ts0 += __shfl_xor_sync(0xffffffffu, ts0, 2);
        ts1 += __shfl_xor_sync(0xffffffffu, ts1, 1);
        ts1 += __shfl_xor_sync(0xffffffffu, ts1, 2);
        rsum0 = rsum0 * corr0 + ts0;
        rsum1 = rsum1 * corr1 + ts1;

        #pragma unroll
        for (int t8 = 0; t8 < 8; t8++) {
            acc[t8][0] *= corr0; acc[t8][1] *= corr0;
            acc[t8][2] *= corr1; acc[t8][3] *= corr1;
        }

        unsigned pah[4][4], pal[4][4];
        #pragma unroll
        for (int s = 0; s < 4; s++) {
            const float* e = sf[2 * s];
            const float* o = sf[2 * s + 1];
            unsigned a0 = packbf(e[0], e[1]);
            unsigned a1 = packbf(e[2], e[3]);
            unsigned a2 = packbf(o[0], o[1]);
            unsigned a3 = packbf(o[2], o[3]);
            pah[s][0] = a0; pah[s][1] = a1; pah[s][2] = a2; pah[s][3] = a3;
            pal[s][0] = packbf(e[0] - bflo(a0), e[1] - bfhi(a0));
            pal[s][1] = packbf(e[2] - bflo(a1), e[3] - bfhi(a1));
            pal[s][2] = packbf(o[0] - bflo(a2), o[1] - bfhi(a2));
            pal[s][3] = packbf(o[2] - bflo(a3), o[3] - bfhi(a3));
        }

        #pragma unroll
        for (int t8 = 0; t8 < 8; t8++) {
            const int rb = (t8 * 8 + lq) * 36;
            unsigned bh[4][2], bl[4][2];
            #pragma unroll
            for (int s = 0; s < 4; s++) {
                bh[s][0] = vh[rb + 8 * s + lr];
                bh[s][1] = vh[rb + 8 * s + 4 + lr];
                bl[s][0] = vl[rb + 8 * s + lr];
                bl[s][1] = vl[rb + 8 * s + 4 + lr];
            }
            #pragma unroll
            for (int s = 0; s < 4; s++) {
                mma_bf16(acc[t8], pah[s], bh[s]);
                mma_bf16(acc[t8], pah[s], bl[s]);
                mma_bf16(acc[t8], pal[s], bh[s]);
            }
        }
    }

    float sc0 = 0.125f / rsum0;
    float sc1 = 0.125f / rsum1;
    int mr0 = q0 + w * 16 + lq;
    size_t base0 = ((size_t)b * T_DIM + mr0) * D_DIM;
    size_t base1 = base0 + 8 * D_DIM;
    #pragma unroll
    for (int t8 = 0; t8 < 8; t8++) {
        int col = 8 * t8 + 2 * lr;
        *reinterpret_cast<float2*>(&out[base0 + col]) =
            make_float2(acc[t8][0] * sc0, acc[t8][1] * sc0);
        *reinterpret_cast<float2*>(&out[base1 + col]) =
            make_float2(acc[t8][2] * sc1, acc[t8][3] * sc1);
    }
}

// ---------------------------------------------------------------------------
extern "C" void kernel_launch(void* const* d_in, const int* in_sizes, int n_in,
                              void* d_out, int out_size)
{
    const float* x  = (const float*)d_in[0];
    const float* Wq = (const float*)d_in[1];
    const float* Wk = (const float*)d_in[2];
    const float* Wv = (const float*)d_in[3];
    float* out = (float*)d_out;

    split_w_kernel<<<384, 256>>>(Wq, Wk, Wv);

    cudaFuncSetAttribute(qkv_mma_kernel,
                         cudaFuncAttributeMaxDynamicSharedMemorySize, QKV_SMEM_BYTES);
    dim3 g1(3, 128);
    qkv_mma_kernel<<<g1, 256, QKV_SMEM_BYTES>>>(x);

    vt_kernel<<<(B_DIM * 64 * 2048) / 256, 256>>>();

    const int smem = 73728;
    cudaFuncSetAttribute(attn_kernel,
                         cudaFuncAttributeMaxDynamicSharedMemorySize, smem);
    dim3 g2(T_DIM / 128, B_DIM);
    attn_kernel<<<g2, 256, smem>>>(out);
}